// round 10
// baseline (speedup 1.0000x reference)
#include <cuda_runtime.h>
#include <cuda_fp16.h>
#include <cuda_pipeline.h>
#include <cstdint>

#define SEQ 1024

// fp16 q/k scratch (allocation-free: __device__ globals)
__device__ __half q_buf[4 * SEQ * 8];
__device__ __half k_buf[4 * SEQ * 8];
// partial-sum scratch: [eighth][n][proj][b][8 comps]
__device__ float part_buf[8 * SEQ * 2 * 4 * 8];

typedef unsigned long long ull;

// ---- packed f32x2 helpers (Blackwell) ----
__device__ __forceinline__ ull pk2(float lo, float hi) {
    ull d;
    asm("mov.b64 %0, {%1, %2};" : "=l"(d)
        : "r"(__float_as_uint(lo)), "r"(__float_as_uint(hi)));
    return d;
}
__device__ __forceinline__ void upk2(ull d, float& lo, float& hi) {
    unsigned a, b;
    asm("mov.b64 {%0, %1}, %2;" : "=r"(a), "=r"(b) : "l"(d));
    lo = __uint_as_float(a); hi = __uint_as_float(b);
}
__device__ __forceinline__ ull f2fma(ull a, ull b, ull c) {
    ull d;
    asm("fma.rn.f32x2 %0, %1, %2, %3;" : "=l"(d) : "l"(a), "l"(b), "l"(c));
    return d;
}
__device__ __forceinline__ ull f2mul(ull a, ull b) {
    ull d;
    asm("mul.rn.f32x2 %0, %1, %2;" : "=l"(d) : "l"(a), "l"(b));
    return d;
}

// ---------------------------------------------------------------------------
// Kernel A1: partial mvlinear, batch-packed f32x2, both projections per warp,
// W streamed through a per-warp 3-stage cp.async pipeline (no W registers in
// flight -> MLP decoupled from register pressure).
// Block = (8 n rows, m-eighth of 128). Warp = one n. Lane = (m_local =
// lane>>1, parity p = lane&1 -> batches {p, p+2} packed in f32x2).
// x staged in smem pre-packed as (x[p,m,i], x[p+2,m,i]) ulls, base 16B-unit
// = m*9 + p*4 (conflict-free). W chunk = 32 m x (wq,wk float4) = 1 KB/stage.
// Truncated butterfly (16,8,4,2) reduces over the 16 same-parity lanes;
// lane l ends with fully-reduced values (l&30) and (l&30)|1.
// ---------------------------------------------------------------------------
__global__ void __launch_bounds__(256) proj_partial_kernel(
    const float* __restrict__ x,     // [4,1024,8]
    const float* __restrict__ Wq,    // [1024,1024,4]
    const float* __restrict__ Wk)    // [1024,1024,4]
{
    __shared__ ull    xs[2304];           // 128 m * 9 units * 16B = 18 KB
    __shared__ float4 ws[8][3][64];       // warp, stage, (wq[32] | wk[32]) = 24 KB

    const int t      = threadIdx.x;
    const int w      = t >> 5;
    const int lane   = t & 31;
    const int p      = lane & 1;
    const int ntile  = blockIdx.x;        // 0..127
    const int eighth = blockIdx.y;        // 0..7
    const int n      = ntile * 8 + w;
    const int q0     = eighth * 128;

    // ---- stage x eighth, batch-pair packed: items (m 0..127, p 0..1) ----
    {
        const float4* x4 = reinterpret_cast<const float4*>(x);
        const int m  = t >> 1;
        const int pp = t & 1;
        const float4 a0 = __ldg(&x4[((size_t)pp * SEQ + q0 + m) * 2]);
        const float4 a1 = __ldg(&x4[((size_t)pp * SEQ + q0 + m) * 2 + 1]);
        const float4 b0 = __ldg(&x4[((size_t)(pp + 2) * SEQ + q0 + m) * 2]);
        const float4 b1 = __ldg(&x4[((size_t)(pp + 2) * SEQ + q0 + m) * 2 + 1]);
        ull* dst = xs + (size_t)(m * 9 + pp * 4) * 2;
        dst[0] = pk2(a0.x, b0.x); dst[1] = pk2(a0.y, b0.y);
        dst[2] = pk2(a0.z, b0.z); dst[3] = pk2(a0.w, b0.w);
        dst[4] = pk2(a1.x, b1.x); dst[5] = pk2(a1.y, b1.y);
        dst[6] = pk2(a1.z, b1.z); dst[7] = pk2(a1.w, b1.w);
    }

    const float4* wqr = reinterpret_cast<const float4*>(Wq) + (size_t)n * SEQ + q0;
    const float4* wkr = reinterpret_cast<const float4*>(Wk) + (size_t)n * SEQ + q0;

    // ---- prologue: issue chunks 0,1 into stages 0,1 ----
#pragma unroll
    for (int c = 0; c < 2; c++) {
        __pipeline_memcpy_async(&ws[w][c][lane],      &wqr[c * 32 + lane], 16);
        __pipeline_memcpy_async(&ws[w][c][32 + lane], &wkr[c * 32 + lane], 16);
        __pipeline_commit();
    }

    ull accq[8], acck[8];
#pragma unroll
    for (int i = 0; i < 8; i++) { accq[i] = 0ull; acck[i] = 0ull; }

    __syncthreads();   // xs visible

#pragma unroll 1
    for (int c = 0; c < 4; c++) {
        __pipeline_wait_prior(1);   // chunk c's group complete
        __syncwarp();

        // issue chunk c+2 into stage (c+2)%3 (stage of chunk c-1, already consumed)
        if (c + 2 < 4) {
            const int s = (c + 2) % 3;
            __pipeline_memcpy_async(&ws[w][s][lane],      &wqr[(c + 2) * 32 + lane], 16);
            __pipeline_memcpy_async(&ws[w][s][32 + lane], &wkr[(c + 2) * 32 + lane], 16);
        }
        __pipeline_commit();        // (empty group when no copies issued)

        const int st = c % 3;
#pragma unroll
        for (int sub = 0; sub < 2; sub++) {
            const int r  = sub * 16 + (lane >> 1);      // row in chunk
            const int ml = c * 32 + r;                  // row in eighth
            const float4 wq = ws[w][st][r];
            const float4 wk = ws[w][st][32 + r];
            const ull* xr = xs + (size_t)(ml * 9 + p * 4) * 2;
            const ull x0 = xr[0], x1 = xr[1], x2 = xr[2], x3 = xr[3];
            const ull x4v = xr[4], x5 = xr[5], x6 = xr[6], x7 = xr[7];

            const ull wq0 = pk2(wq.x, wq.x), wq1 = pk2(wq.y, wq.y),
                      wq2 = pk2(wq.z, wq.z), wq3 = pk2(wq.w, wq.w);
            const ull wk0 = pk2(wk.x, wk.x), wk1 = pk2(wk.y, wk.y),
                      wk2 = pk2(wk.z, wk.z), wk3 = pk2(wk.w, wk.w);

            accq[0] = f2fma(wq0, x0,  accq[0]);  acck[0] = f2fma(wk0, x0,  acck[0]);
            accq[1] = f2fma(wq1, x1,  accq[1]);  acck[1] = f2fma(wk1, x1,  acck[1]);
            accq[2] = f2fma(wq1, x2,  accq[2]);  acck[2] = f2fma(wk1, x2,  acck[2]);
            accq[3] = f2fma(wq1, x3,  accq[3]);  acck[3] = f2fma(wk1, x3,  acck[3]);
            accq[4] = f2fma(wq2, x4v, accq[4]);  acck[4] = f2fma(wk2, x4v, acck[4]);
            accq[5] = f2fma(wq2, x5,  accq[5]);  acck[5] = f2fma(wk2, x5,  acck[5]);
            accq[6] = f2fma(wq2, x6,  accq[6]);  acck[6] = f2fma(wk2, x6,  acck[6]);
            accq[7] = f2fma(wq3, x7,  accq[7]);  acck[7] = f2fma(wk3, x7,  acck[7]);
        }
    }

    // Unpack: arr[v], v = pj*16 + bl*8 + i  (bl=0 -> b=p, bl=1 -> b=p+2)
    float arr[32];
#pragma unroll
    for (int i = 0; i < 8; i++) {
        upk2(accq[i], arr[i],      arr[8 + i]);
        upk2(acck[i], arr[16 + i], arr[24 + i]);
    }

    // Truncated butterfly: offsets 16,8,4,2 -> reduce over 16 same-parity
    // lanes; lane l ends with values (l&30) and (l&30)|1.
#pragma unroll
    for (int off = 16; off >= 2; off >>= 1) {
        const bool up = (lane & off) != 0;
#pragma unroll
        for (int k = 0; k < 16; k++) {
            if (k < off) {
                float send  = up ? arr[k] : arr[k + off];
                float other = __shfl_xor_sync(0xffffffffu, send, off);
                arr[k] = (up ? arr[k + off] : arr[k]) + other;
            }
        }
    }

    const int vbase = lane & 30;
#pragma unroll
    for (int k = 0; k < 2; k++) {
        const int v  = vbase | k;
        const int pj = v >> 4;
        const int bl = (v >> 3) & 1;
        const int i  = v & 7;
        const int b  = p + 2 * bl;
        part_buf[(((size_t)eighth * SEQ + n) * 2 + pj) * 32 + b * 8 + i] = arr[k];
    }
}

// ---------------------------------------------------------------------------
// Kernel A2: combine the 8 m-eighth partials, add bias, LayerNorm, fp16
// cast. One thread per (n, proj, b) = 8192 threads.
// ---------------------------------------------------------------------------
__global__ void __launch_bounds__(256) ln_finalize_kernel(
    const float* __restrict__ bq,
    const float* __restrict__ bk,
    const float* __restrict__ gamma,
    const float* __restrict__ beta)
{
    const int t  = blockIdx.x * 256 + threadIdx.x;
    const int n  = t >> 3;
    const int pj = (t >> 2) & 1;
    const int b  = t & 3;

    float v[8];
#pragma unroll
    for (int i = 0; i < 8; i++) v[i] = 0.0f;
#pragma unroll
    for (int q = 0; q < 8; q++) {
        const float* p = part_buf + (((size_t)q * SEQ + n) * 2 + pj) * 32 + b * 8;
#pragma unroll
        for (int i = 0; i < 8; i++) v[i] += p[i];
    }
    v[0] += pj ? bk[n] : bq[n];   // bias on scalar comp, before LN

    float mu = 0.0f;
#pragma unroll
    for (int i = 0; i < 8; i++) mu += v[i];
    mu *= 0.125f;
    float var = 0.0f;
#pragma unroll
    for (int i = 0; i < 8; i++) { float d = v[i] - mu; var = fmaf(d, d, var); }
    const float r = rsqrtf(var * 0.125f + 1e-5f);

    __half2* dst = reinterpret_cast<__half2*>(
        (pj ? k_buf : q_buf) + ((size_t)b * SEQ + n) * 8);
#pragma unroll
    for (int j = 0; j < 4; j++) {
        float a0 = (v[2*j]   - mu) * r * gamma[2*j]   + beta[2*j];
        float a1 = (v[2*j+1] - mu) * r * gamma[2*j+1] + beta[2*j+1];
        dst[j] = __floats2half2_rn(a0, a1);
    }
}

// ---------------------------------------------------------------------------
// Kernel B: geometric product out[b,n,m,:] = GP(q[b,n], k[b,m]), Cl(3,0),
// basis [1, e1, e2, e3, e12, e13, e23, e123].
// Even lanes compute comps 0..3, odd lanes comps 4..7 via duality
// out o (-e123). Thread covers m-pair (m_a, m_a+16) in f32x2 lanes; each
// warp-STG is 512B contiguous. 16 n-rows per block, q tile pre-packed as
// (q,q) ulls in smem -> per-nl broadcast LDS.64.
// ---------------------------------------------------------------------------
__global__ void __launch_bounds__(256) gp_kernel(float* __restrict__ out)
{
    __shared__ ull qsp[16][8];

    const int b      = blockIdx.y;
    const int ntile  = blockIdx.x >> 2;     // 0..63
    const int mchunk = blockIdx.x & 3;      // 0..3
    const int n0     = ntile * 16;
    const int t      = threadIdx.x;
    const int w      = t >> 5;
    const int lane   = t & 31;
    const int half   = lane & 1;            // 0: comps 0-3, 1: comps 4-7
    const int mm     = lane >> 1;           // 0..15
    const int m_a    = mchunk * 256 + w * 32 + mm;   // pair partner: m_a + 16

    // q tile: 16 rows x 8 comps, stored duplicated-packed for direct LDS.64
    if (t < 128) {
        const float v = __half2float(
            q_buf[((size_t)b * SEQ + n0 + (t >> 3)) * 8 + (t & 7)]);
        qsp[t >> 3][t & 7] = pk2(v, v);
    }

    // K for both m's of this thread
    const uint4* kb4 = reinterpret_cast<const uint4*>(k_buf) + (size_t)b * SEQ;
    const uint4 kva = __ldg(&kb4[m_a]);
    const uint4 kvb = __ldg(&kb4[m_a + 16]);

    float A[8], B[8];
    {
        float2 f;
        f = __half22float2(*reinterpret_cast<const __half2*>(&kva.x)); A[0]=f.x; A[1]=f.y;
        f = __half22float2(*reinterpret_cast<const __half2*>(&kva.y)); A[2]=f.x; A[3]=f.y;
        f = __half22float2(*reinterpret_cast<const __half2*>(&kva.z)); A[4]=f.x; A[5]=f.y;
        f = __half22float2(*reinterpret_cast<const __half2*>(&kva.w)); A[6]=f.x; A[7]=f.y;
        f = __half22float2(*reinterpret_cast<const __half2*>(&kvb.x)); B[0]=f.x; B[1]=f.y;
        f = __half22float2(*reinterpret_cast<const __half2*>(&kvb.y)); B[2]=f.x; B[3]=f.y;
        f = __half22float2(*reinterpret_cast<const __half2*>(&kvb.z)); B[4]=f.x; B[5]=f.y;
        f = __half22float2(*reinterpret_cast<const __half2*>(&kvb.w)); B[6]=f.x; B[7]=f.y;
    }
    if (half) {  // K' = k o (-e123): {k7, k6, -k5, k4, -k3, k2, -k1, -k0}
        float tA[8], tB[8];
        tA[0]= A[7]; tA[1]= A[6]; tA[2]=-A[5]; tA[3]= A[4];
        tA[4]=-A[3]; tA[5]= A[2]; tA[6]=-A[1]; tA[7]=-A[0];
        tB[0]= B[7]; tB[1]= B[6]; tB[2]=-B[5]; tB[3]= B[4];
        tB[4]=-B[3]; tB[5]= B[2]; tB[6]=-B[1]; tB[7]=-B[0];
#pragma unroll
        for (int i = 0; i < 8; i++) { A[i] = tA[i]; B[i] = tB[i]; }
    }
    const ull K0 = pk2(A[0],B[0]), K1 = pk2(A[1],B[1]), K2 = pk2(A[2],B[2]),
              K3 = pk2(A[3],B[3]), K4 = pk2(A[4],B[4]), K5 = pk2(A[5],B[5]),
              K6 = pk2(A[6],B[6]), K7 = pk2(A[7],B[7]);
    const ull NK1 = pk2(-A[1],-B[1]), NK2 = pk2(-A[2],-B[2]),
              NK4 = pk2(-A[4],-B[4]), NK5 = pk2(-A[5],-B[5]),
              NK6 = pk2(-A[6],-B[6]), NK7 = pk2(-A[7],-B[7]);
    const ull MNEG1 = pk2(-1.0f, -1.0f);

    __syncthreads();

    // float4 index of this thread's first chunk for nl=0
    size_t fi = ((size_t)(b * SEQ + n0) * SEQ + m_a) * 2 + half;
    float4* o4 = reinterpret_cast<float4*>(out);

#pragma unroll 1
    for (int nl = 0; nl < 16; nl++) {
        const ull P0 = qsp[nl][0], P1 = qsp[nl][1], P2 = qsp[nl][2], P3 = qsp[nl][3],
                  P4 = qsp[nl][4], P5 = qsp[nl][5], P6 = qsp[nl][6], P7 = qsp[nl][7];

        // o0..o3 of q o K (verified table; odd lanes' K is pre-transformed)
        ull a0 = f2mul(P0, K0);
        ull a1 = f2mul(P0, K1);
        ull a2 = f2mul(P0, K2);
        ull a3 = f2mul(P0, K3);
        a0 = f2fma(P1, K1,  a0); a1 = f2fma(P1, K0,  a1); a2 = f2fma(P1, K4,  a2); a3 = f2fma(P1, K5,  a3);
        a0 = f2fma(P2, K2,  a0); a1 = f2fma(P2, NK4, a1); a2 = f2fma(P2, K0,  a2); a3 = f2fma(P2, K6,  a3);
        a0 = f2fma(P3, K3,  a0); a1 = f2fma(P3, NK5, a1); a2 = f2fma(P3, NK6, a2); a3 = f2fma(P3, K0,  a3);
        a0 = f2fma(P4, NK4, a0); a1 = f2fma(P4, K2,  a1); a2 = f2fma(P4, NK1, a2); a3 = f2fma(P4, NK7, a3);
        a0 = f2fma(P5, NK5, a0); a1 = f2fma(P5, K3,  a1); a2 = f2fma(P5, K7,  a2); a3 = f2fma(P5, NK1, a3);
        a0 = f2fma(P6, NK6, a0); a1 = f2fma(P6, NK7, a1); a2 = f2fma(P6, K3,  a2); a3 = f2fma(P6, NK2, a3);
        a0 = f2fma(P7, NK7, a0); a1 = f2fma(P7, NK6, a1); a2 = f2fma(P7, K5,  a2); a3 = f2fma(P7, NK4, a3);

        // odd lanes: (out4,out5,out6,out7) = (o3, -o2, o1, o0)
        const ull na2 = f2mul(a2, MNEG1);
        const ull s0 = half ? a3  : a0;
        const ull s1 = half ? na2 : a1;
        const ull s2 = half ? a1  : a2;
        const ull s3 = half ? a0  : a3;

        float e0,e1,e2,e3, f0,f1,f2,f3;
        upk2(s0, e0, f0); upk2(s1, e1, f1); upk2(s2, e2, f2); upk2(s3, e3, f3);

        __stcs(&o4[fi],      make_float4(e0, e1, e2, e3));   // m_a
        __stcs(&o4[fi + 32], make_float4(f0, f1, f2, f3));   // m_a + 16
        fi += 2048;   // next n row
    }
}

extern "C" void kernel_launch(void* const* d_in, const int* in_sizes, int n_in,
                              void* d_out, int out_size)
{
    (void)in_sizes; (void)n_in; (void)out_size;
    const float* x     = (const float*)d_in[0];
    const float* Wq    = (const float*)d_in[1];
    const float* bq    = (const float*)d_in[2];
    const float* Wk    = (const float*)d_in[3];
    const float* bk    = (const float*)d_in[4];
    const float* gamma = (const float*)d_in[5];
    const float* beta  = (const float*)d_in[6];
    float* out = (float*)d_out;

    proj_partial_kernel<<<dim3(128, 8), 256>>>(x, Wq, Wk);
    ln_finalize_kernel<<<32, 256>>>(bq, bk, gamma, beta);
    gp_kernel<<<dim3(256, 4), 256>>>(out);
}

// round 13
// speedup vs baseline: 1.0516x; 1.0516x over previous
#include <cuda_runtime.h>
#include <cuda_fp16.h>
#include <cuda_pipeline.h>
#include <cstdint>

#define SEQ 1024

// fp16 q/k scratch (allocation-free: __device__ globals)
__device__ __half q_buf[4 * SEQ * 8];
__device__ __half k_buf[4 * SEQ * 8];
// partial-sum scratch: [eighth][n][proj][b][8 comps]
__device__ float part_buf[8 * SEQ * 2 * 4 * 8];

typedef unsigned long long ull;

// ---- packed f32x2 helpers (Blackwell) ----
__device__ __forceinline__ ull pk2(float lo, float hi) {
    ull d;
    asm("mov.b64 %0, {%1, %2};" : "=l"(d)
        : "r"(__float_as_uint(lo)), "r"(__float_as_uint(hi)));
    return d;
}
__device__ __forceinline__ void upk2(ull d, float& lo, float& hi) {
    unsigned a, b;
    asm("mov.b64 {%0, %1}, %2;" : "=r"(a), "=r"(b) : "l"(d));
    lo = __uint_as_float(a); hi = __uint_as_float(b);
}
__device__ __forceinline__ ull f2fma(ull a, ull b, ull c) {
    ull d;
    asm("fma.rn.f32x2 %0, %1, %2, %3;" : "=l"(d) : "l"(a), "l"(b), "l"(c));
    return d;
}
__device__ __forceinline__ ull f2mul(ull a, ull b) {
    ull d;
    asm("mul.rn.f32x2 %0, %1, %2;" : "=l"(d) : "l"(a), "l"(b));
    return d;
}

// ---------------------------------------------------------------------------
// Kernel A1: partial mvlinear, batch-packed f32x2, both projections per warp,
// W streamed through a per-warp 3-stage cp.async pipeline (no W registers in
// flight -> MLP decoupled from register pressure).
// Block = (8 n rows, m-eighth of 128). Warp = one n. Lane = (m_local =
// lane>>1, parity p = lane&1 -> batches {p, p+2} packed in f32x2).
// __launch_bounds__(256,4) clamps regs to 64 -> 4 blocks/SM (32 warps/SM).
// ---------------------------------------------------------------------------
__global__ void __launch_bounds__(256, 4) proj_partial_kernel(
    const float* __restrict__ x,     // [4,1024,8]
    const float* __restrict__ Wq,    // [1024,1024,4]
    const float* __restrict__ Wk)    // [1024,1024,4]
{
    __shared__ ull    xs[2304];           // 128 m * 9 units * 16B = 18 KB
    __shared__ float4 ws[8][3][64];       // warp, stage, (wq[32] | wk[32]) = 24 KB

    const int t      = threadIdx.x;
    const int w      = t >> 5;
    const int lane   = t & 31;
    const int p      = lane & 1;
    const int ntile  = blockIdx.x;        // 0..127
    const int eighth = blockIdx.y;        // 0..7
    const int n      = ntile * 8 + w;
    const int q0     = eighth * 128;

    // ---- stage x eighth, batch-pair packed: items (m 0..127, p 0..1) ----
    {
        const float4* x4 = reinterpret_cast<const float4*>(x);
        const int m  = t >> 1;
        const int pp = t & 1;
        const float4 a0 = __ldg(&x4[((size_t)pp * SEQ + q0 + m) * 2]);
        const float4 a1 = __ldg(&x4[((size_t)pp * SEQ + q0 + m) * 2 + 1]);
        const float4 b0 = __ldg(&x4[((size_t)(pp + 2) * SEQ + q0 + m) * 2]);
        const float4 b1 = __ldg(&x4[((size_t)(pp + 2) * SEQ + q0 + m) * 2 + 1]);
        ull* dst = xs + (size_t)(m * 9 + pp * 4) * 2;
        dst[0] = pk2(a0.x, b0.x); dst[1] = pk2(a0.y, b0.y);
        dst[2] = pk2(a0.z, b0.z); dst[3] = pk2(a0.w, b0.w);
        dst[4] = pk2(a1.x, b1.x); dst[5] = pk2(a1.y, b1.y);
        dst[6] = pk2(a1.z, b1.z); dst[7] = pk2(a1.w, b1.w);
    }

    const float4* wqr = reinterpret_cast<const float4*>(Wq) + (size_t)n * SEQ + q0;
    const float4* wkr = reinterpret_cast<const float4*>(Wk) + (size_t)n * SEQ + q0;

    // ---- prologue: issue chunks 0,1 into stages 0,1 ----
#pragma unroll
    for (int c = 0; c < 2; c++) {
        __pipeline_memcpy_async(&ws[w][c][lane],      &wqr[c * 32 + lane], 16);
        __pipeline_memcpy_async(&ws[w][c][32 + lane], &wkr[c * 32 + lane], 16);
        __pipeline_commit();
    }

    ull accq[8], acck[8];
#pragma unroll
    for (int i = 0; i < 8; i++) { accq[i] = 0ull; acck[i] = 0ull; }

    __syncthreads();   // xs visible

#pragma unroll 1
    for (int c = 0; c < 4; c++) {
        __pipeline_wait_prior(1);   // chunk c's group complete
        __syncwarp();

        // issue chunk c+2 into stage (c+2)%3 (stage of chunk c-1, already consumed)
        if (c + 2 < 4) {
            const int s = (c + 2) % 3;
            __pipeline_memcpy_async(&ws[w][s][lane],      &wqr[(c + 2) * 32 + lane], 16);
            __pipeline_memcpy_async(&ws[w][s][32 + lane], &wkr[(c + 2) * 32 + lane], 16);
        }
        __pipeline_commit();        // (empty group when no copies issued)

        const int st = c % 3;
#pragma unroll
        for (int sub = 0; sub < 2; sub++) {
            const int r  = sub * 16 + (lane >> 1);      // row in chunk
            const int ml = c * 32 + r;                  // row in eighth
            const float4 wq = ws[w][st][r];
            const float4 wk = ws[w][st][32 + r];
            const ull* xr = xs + (size_t)(ml * 9 + p * 4) * 2;
            const ull x0 = xr[0], x1 = xr[1], x2 = xr[2], x3 = xr[3];
            const ull x4v = xr[4], x5 = xr[5], x6 = xr[6], x7 = xr[7];

            const ull wq0 = pk2(wq.x, wq.x), wq1 = pk2(wq.y, wq.y),
                      wq2 = pk2(wq.z, wq.z), wq3 = pk2(wq.w, wq.w);
            const ull wk0 = pk2(wk.x, wk.x), wk1 = pk2(wk.y, wk.y),
                      wk2 = pk2(wk.z, wk.z), wk3 = pk2(wk.w, wk.w);

            accq[0] = f2fma(wq0, x0,  accq[0]);  acck[0] = f2fma(wk0, x0,  acck[0]);
            accq[1] = f2fma(wq1, x1,  accq[1]);  acck[1] = f2fma(wk1, x1,  acck[1]);
            accq[2] = f2fma(wq1, x2,  accq[2]);  acck[2] = f2fma(wk1, x2,  acck[2]);
            accq[3] = f2fma(wq1, x3,  accq[3]);  acck[3] = f2fma(wk1, x3,  acck[3]);
            accq[4] = f2fma(wq2, x4v, accq[4]);  acck[4] = f2fma(wk2, x4v, acck[4]);
            accq[5] = f2fma(wq2, x5,  accq[5]);  acck[5] = f2fma(wk2, x5,  acck[5]);
            accq[6] = f2fma(wq2, x6,  accq[6]);  acck[6] = f2fma(wk2, x6,  acck[6]);
            accq[7] = f2fma(wq3, x7,  accq[7]);  acck[7] = f2fma(wk3, x7,  acck[7]);
        }
    }

    // Unpack: arr[v], v = pj*16 + bl*8 + i  (bl=0 -> b=p, bl=1 -> b=p+2)
    float arr[32];
#pragma unroll
    for (int i = 0; i < 8; i++) {
        upk2(accq[i], arr[i],      arr[8 + i]);
        upk2(acck[i], arr[16 + i], arr[24 + i]);
    }

    // Truncated butterfly: offsets 16,8,4,2 -> reduce over the 16 same-parity
    // lanes; lane l ends with values (l&30) and (l&30)|1.
#pragma unroll
    for (int off = 16; off >= 2; off >>= 1) {
        const bool up = (lane & off) != 0;
#pragma unroll
        for (int k = 0; k < 16; k++) {
            if (k < off) {
                float send  = up ? arr[k] : arr[k + off];
                float other = __shfl_xor_sync(0xffffffffu, send, off);
                arr[k] = (up ? arr[k + off] : arr[k]) + other;
            }
        }
    }

    const int vbase = lane & 30;
#pragma unroll
    for (int k = 0; k < 2; k++) {
        const int v  = vbase | k;
        const int pj = v >> 4;
        const int bl = (v >> 3) & 1;
        const int i  = v & 7;
        const int b  = p + 2 * bl;
        part_buf[(((size_t)eighth * SEQ + n) * 2 + pj) * 32 + b * 8 + i] = arr[k];
    }
}

// ---------------------------------------------------------------------------
// Kernel A2: combine the 8 m-eighth partials, add bias, LayerNorm, fp16
// cast. One thread per (n, proj, b) = 8192 threads.
// ---------------------------------------------------------------------------
__global__ void __launch_bounds__(256) ln_finalize_kernel(
    const float* __restrict__ bq,
    const float* __restrict__ bk,
    const float* __restrict__ gamma,
    const float* __restrict__ beta)
{
    const int t  = blockIdx.x * 256 + threadIdx.x;
    const int n  = t >> 3;
    const int pj = (t >> 2) & 1;
    const int b  = t & 3;

    float v[8];
#pragma unroll
    for (int i = 0; i < 8; i++) v[i] = 0.0f;
#pragma unroll
    for (int q = 0; q < 8; q++) {
        const float* p = part_buf + (((size_t)q * SEQ + n) * 2 + pj) * 32 + b * 8;
#pragma unroll
        for (int i = 0; i < 8; i++) v[i] += p[i];
    }
    v[0] += pj ? bk[n] : bq[n];   // bias on scalar comp, before LN

    float mu = 0.0f;
#pragma unroll
    for (int i = 0; i < 8; i++) mu += v[i];
    mu *= 0.125f;
    float var = 0.0f;
#pragma unroll
    for (int i = 0; i < 8; i++) { float d = v[i] - mu; var = fmaf(d, d, var); }
    const float r = rsqrtf(var * 0.125f + 1e-5f);

    __half2* dst = reinterpret_cast<__half2*>(
        (pj ? k_buf : q_buf) + ((size_t)b * SEQ + n) * 8);
#pragma unroll
    for (int j = 0; j < 4; j++) {
        float a0 = (v[2*j]   - mu) * r * gamma[2*j]   + beta[2*j];
        float a1 = (v[2*j+1] - mu) * r * gamma[2*j+1] + beta[2*j+1];
        dst[j] = __floats2half2_rn(a0, a1);
    }
}

// ---------------------------------------------------------------------------
// Kernel B: geometric product out[b,n,m,:] = GP(q[b,n], k[b,m]), Cl(3,0),
// basis [1, e1, e2, e3, e12, e13, e23, e123].
// Even lanes compute comps 0..3, odd lanes comps 4..7 via duality
// out o (-e123). Thread covers m-pair (m_a, m_a+16) in f32x2 lanes; each
// warp-STG is 512B contiguous. 8 n-rows per block (2048 blocks), q tile
// pre-packed as (q,q) ulls in smem -> per-nl broadcast LDS.64.
// ---------------------------------------------------------------------------
__global__ void __launch_bounds__(256) gp_kernel(float* __restrict__ out)
{
    __shared__ ull qsp[8][8];

    const int b      = blockIdx.y;
    const int ntile  = blockIdx.x >> 2;     // 0..127
    const int mchunk = blockIdx.x & 3;      // 0..3
    const int n0     = ntile * 8;
    const int t      = threadIdx.x;
    const int w      = t >> 5;
    const int lane   = t & 31;
    const int half   = lane & 1;            // 0: comps 0-3, 1: comps 4-7
    const int mm     = lane >> 1;           // 0..15
    const int m_a    = mchunk * 256 + w * 32 + mm;   // pair partner: m_a + 16

    // q tile: 8 rows x 8 comps, stored duplicated-packed for direct LDS.64
    if (t < 64) {
        const float v = __half2float(
            q_buf[((size_t)b * SEQ + n0 + (t >> 3)) * 8 + (t & 7)]);
        qsp[t >> 3][t & 7] = pk2(v, v);
    }

    // K for both m's of this thread
    const uint4* kb4 = reinterpret_cast<const uint4*>(k_buf) + (size_t)b * SEQ;
    const uint4 kva = __ldg(&kb4[m_a]);
    const uint4 kvb = __ldg(&kb4[m_a + 16]);

    float A[8], B[8];
    {
        float2 f;
        f = __half22float2(*reinterpret_cast<const __half2*>(&kva.x)); A[0]=f.x; A[1]=f.y;
        f = __half22float2(*reinterpret_cast<const __half2*>(&kva.y)); A[2]=f.x; A[3]=f.y;
        f = __half22float2(*reinterpret_cast<const __half2*>(&kva.z)); A[4]=f.x; A[5]=f.y;
        f = __half22float2(*reinterpret_cast<const __half2*>(&kva.w)); A[6]=f.x; A[7]=f.y;
        f = __half22float2(*reinterpret_cast<const __half2*>(&kvb.x)); B[0]=f.x; B[1]=f.y;
        f = __half22float2(*reinterpret_cast<const __half2*>(&kvb.y)); B[2]=f.x; B[3]=f.y;
        f = __half22float2(*reinterpret_cast<const __half2*>(&kvb.z)); B[4]=f.x; B[5]=f.y;
        f = __half22float2(*reinterpret_cast<const __half2*>(&kvb.w)); B[6]=f.x; B[7]=f.y;
    }
    if (half) {  // K' = k o (-e123): {k7, k6, -k5, k4, -k3, k2, -k1, -k0}
        float tA[8], tB[8];
        tA[0]= A[7]; tA[1]= A[6]; tA[2]=-A[5]; tA[3]= A[4];
        tA[4]=-A[3]; tA[5]= A[2]; tA[6]=-A[1]; tA[7]=-A[0];
        tB[0]= B[7]; tB[1]= B[6]; tB[2]=-B[5]; tB[3]= B[4];
        tB[4]=-B[3]; tB[5]= B[2]; tB[6]=-B[1]; tB[7]=-B[0];
#pragma unroll
        for (int i = 0; i < 8; i++) { A[i] = tA[i]; B[i] = tB[i]; }
    }
    const ull K0 = pk2(A[0],B[0]), K1 = pk2(A[1],B[1]), K2 = pk2(A[2],B[2]),
              K3 = pk2(A[3],B[3]), K4 = pk2(A[4],B[4]), K5 = pk2(A[5],B[5]),
              K6 = pk2(A[6],B[6]), K7 = pk2(A[7],B[7]);
    const ull NK1 = pk2(-A[1],-B[1]), NK2 = pk2(-A[2],-B[2]),
              NK4 = pk2(-A[4],-B[4]), NK5 = pk2(-A[5],-B[5]),
              NK6 = pk2(-A[6],-B[6]), NK7 = pk2(-A[7],-B[7]);
    const ull MNEG1 = pk2(-1.0f, -1.0f);

    __syncthreads();

    // float4 index of this thread's first chunk for nl=0
    size_t fi = ((size_t)(b * SEQ + n0) * SEQ + m_a) * 2 + half;
    float4* o4 = reinterpret_cast<float4*>(out);

#pragma unroll 1
    for (int nl = 0; nl < 8; nl++) {
        const ull P0 = qsp[nl][0], P1 = qsp[nl][1], P2 = qsp[nl][2], P3 = qsp[nl][3],
                  P4 = qsp[nl][4], P5 = qsp[nl][5], P6 = qsp[nl][6], P7 = qsp[nl][7];

        // o0..o3 of q o K (verified table; odd lanes' K is pre-transformed)
        ull a0 = f2mul(P0, K0);
        ull a1 = f2mul(P0, K1);
        ull a2 = f2mul(P0, K2);
        ull a3 = f2mul(P0, K3);
        a0 = f2fma(P1, K1,  a0); a1 = f2fma(P1, K0,  a1); a2 = f2fma(P1, K4,  a2); a3 = f2fma(P1, K5,  a3);
        a0 = f2fma(P2, K2,  a0); a1 = f2fma(P2, NK4, a1); a2 = f2fma(P2, K0,  a2); a3 = f2fma(P2, K6,  a3);
        a0 = f2fma(P3, K3,  a0); a1 = f2fma(P3, NK5, a1); a2 = f2fma(P3, NK6, a2); a3 = f2fma(P3, K0,  a3);
        a0 = f2fma(P4, NK4, a0); a1 = f2fma(P4, K2,  a1); a2 = f2fma(P4, NK1, a2); a3 = f2fma(P4, NK7, a3);
        a0 = f2fma(P5, NK5, a0); a1 = f2fma(P5, K3,  a1); a2 = f2fma(P5, K7,  a2); a3 = f2fma(P5, NK1, a3);
        a0 = f2fma(P6, NK6, a0); a1 = f2fma(P6, NK7, a1); a2 = f2fma(P6, K3,  a2); a3 = f2fma(P6, NK2, a3);
        a0 = f2fma(P7, NK7, a0); a1 = f2fma(P7, NK6, a1); a2 = f2fma(P7, K5,  a2); a3 = f2fma(P7, NK4, a3);

        // odd lanes: (out4,out5,out6,out7) = (o3, -o2, o1, o0)
        const ull na2 = f2mul(a2, MNEG1);
        const ull s0 = half ? a3  : a0;
        const ull s1 = half ? na2 : a1;
        const ull s2 = half ? a1  : a2;
        const ull s3 = half ? a0  : a3;

        float e0,e1,e2,e3, f0,f1,f2,f3;
        upk2(s0, e0, f0); upk2(s1, e1, f1); upk2(s2, e2, f2); upk2(s3, e3, f3);

        __stcs(&o4[fi],      make_float4(e0, e1, e2, e3));   // m_a
        __stcs(&o4[fi + 32], make_float4(f0, f1, f2, f3));   // m_a + 16
        fi += 2048;   // next n row
    }
}

extern "C" void kernel_launch(void* const* d_in, const int* in_sizes, int n_in,
                              void* d_out, int out_size)
{
    (void)in_sizes; (void)n_in; (void)out_size;
    const float* x     = (const float*)d_in[0];
    const float* Wq    = (const float*)d_in[1];
    const float* bq    = (const float*)d_in[2];
    const float* Wk    = (const float*)d_in[3];
    const float* bk    = (const float*)d_in[4];
    const float* gamma = (const float*)d_in[5];
    const float* beta  = (const float*)d_in[6];
    float* out = (float*)d_out;

    proj_partial_kernel<<<dim3(128, 8), 256>>>(x, Wq, Wk);
    ln_finalize_kernel<<<32, 256>>>(bq, bk, gamma, beta);
    gp_kernel<<<dim3(512, 4), 256>>>(out);
}

// round 15
// speedup vs baseline: 1.0567x; 1.0049x over previous
#include <cuda_runtime.h>
#include <cuda_fp16.h>
#include <cuda_pipeline.h>
#include <cstdint>

#define SEQ 1024

// fp16 q/k scratch (allocation-free: __device__ globals)
__device__ __half q_buf[4 * SEQ * 8];
__device__ __half k_buf[4 * SEQ * 8];
// partial-sum scratch: [eighth][n][proj][b][8 comps]
__device__ float part_buf[8 * SEQ * 2 * 4 * 8];

typedef unsigned long long ull;

// dynamic smem layout for proj: xs (2304 ull = 18KB) then ws (2048 float4 = 32KB)
#define PROJ_SMEM_BYTES (2304 * 8 + 8 * 4 * 64 * 16)

// ---- packed f32x2 helpers (Blackwell) ----
__device__ __forceinline__ ull pk2(float lo, float hi) {
    ull d;
    asm("mov.b64 %0, {%1, %2};" : "=l"(d)
        : "r"(__float_as_uint(lo)), "r"(__float_as_uint(hi)));
    return d;
}
__device__ __forceinline__ void upk2(ull d, float& lo, float& hi) {
    unsigned a, b;
    asm("mov.b64 {%0, %1}, %2;" : "=r"(a), "=r"(b) : "l"(d));
    lo = __uint_as_float(a); hi = __uint_as_float(b);
}
__device__ __forceinline__ ull f2fma(ull a, ull b, ull c) {
    ull d;
    asm("fma.rn.f32x2 %0, %1, %2, %3;" : "=l"(d) : "l"(a), "l"(b), "l"(c));
    return d;
}
__device__ __forceinline__ ull f2mul(ull a, ull b) {
    ull d;
    asm("mul.rn.f32x2 %0, %1, %2;" : "=l"(d) : "l"(a), "l"(b));
    return d;
}

// ---------------------------------------------------------------------------
// Kernel A1: partial mvlinear, batch-packed f32x2, both projections per warp,
// W fully prefetched through a 4-deep cp.async pipeline (all 4 chunks issued
// before the main loop; loop only waits and consumes). Dynamic smem (50 KB)
// to clear the 48 KB static limit; 4 blocks/SM = 200 KB of the 228 KB carveout.
// Block = (8 n rows, m-eighth of 128). Warp = one n. Lane = (m_local =
// lane>>1, parity p = lane&1 -> batches {p, p+2} packed in f32x2).
// ---------------------------------------------------------------------------
__global__ void __launch_bounds__(256, 4) proj_partial_kernel(
    const float* __restrict__ x,     // [4,1024,8]
    const float* __restrict__ Wq,    // [1024,1024,4]
    const float* __restrict__ Wk)    // [1024,1024,4]
{
    extern __shared__ ull dyn_smem[];
    ull*    xs = dyn_smem;                                   // 128 m * 9 units * 16B
    float4* ws = reinterpret_cast<float4*>(dyn_smem + 2304); // [warp][stage][64]

    const int t      = threadIdx.x;
    const int w      = t >> 5;
    const int lane   = t & 31;
    const int p      = lane & 1;
    const int ntile  = blockIdx.x;        // 0..127
    const int eighth = blockIdx.y;        // 0..7
    const int n      = ntile * 8 + w;
    const int q0     = eighth * 128;

    const float4* wqr = reinterpret_cast<const float4*>(Wq) + (size_t)n * SEQ + q0;
    const float4* wkr = reinterpret_cast<const float4*>(Wk) + (size_t)n * SEQ + q0;
    float4* wsw = ws + w * 4 * 64;

    // ---- prologue: issue ALL 4 W chunks into 4 stages ----
#pragma unroll
    for (int c = 0; c < 4; c++) {
        __pipeline_memcpy_async(&wsw[c * 64 + lane],      &wqr[c * 32 + lane], 16);
        __pipeline_memcpy_async(&wsw[c * 64 + 32 + lane], &wkr[c * 32 + lane], 16);
        __pipeline_commit();
    }

    // ---- stage x eighth, batch-pair packed: items (m 0..127, p 0..1) ----
    {
        const float4* x4 = reinterpret_cast<const float4*>(x);
        const int m  = t >> 1;
        const int pp = t & 1;
        const float4 a0 = __ldg(&x4[((size_t)pp * SEQ + q0 + m) * 2]);
        const float4 a1 = __ldg(&x4[((size_t)pp * SEQ + q0 + m) * 2 + 1]);
        const float4 b0 = __ldg(&x4[((size_t)(pp + 2) * SEQ + q0 + m) * 2]);
        const float4 b1 = __ldg(&x4[((size_t)(pp + 2) * SEQ + q0 + m) * 2 + 1]);
        ull* dst = xs + (size_t)(m * 9 + pp * 4) * 2;
        dst[0] = pk2(a0.x, b0.x); dst[1] = pk2(a0.y, b0.y);
        dst[2] = pk2(a0.z, b0.z); dst[3] = pk2(a0.w, b0.w);
        dst[4] = pk2(a1.x, b1.x); dst[5] = pk2(a1.y, b1.y);
        dst[6] = pk2(a1.z, b1.z); dst[7] = pk2(a1.w, b1.w);
    }

    ull accq[8], acck[8];
#pragma unroll
    for (int i = 0; i < 8; i++) { accq[i] = 0ull; acck[i] = 0ull; }

    __syncthreads();   // xs visible

#pragma unroll
    for (int c = 0; c < 4; c++) {
        __pipeline_wait_prior(3 - c);   // chunk c's group complete
        __syncwarp();

#pragma unroll
        for (int sub = 0; sub < 2; sub++) {
            const int r  = sub * 16 + (lane >> 1);      // row in chunk
            const int ml = c * 32 + r;                  // row in eighth
            const float4 wq = wsw[c * 64 + r];
            const float4 wk = wsw[c * 64 + 32 + r];
            const ull* xr = xs + (size_t)(ml * 9 + p * 4) * 2;
            const ull x0 = xr[0], x1 = xr[1], x2 = xr[2], x3 = xr[3];
            const ull x4v = xr[4], x5 = xr[5], x6 = xr[6], x7 = xr[7];

            const ull wq0 = pk2(wq.x, wq.x), wq1 = pk2(wq.y, wq.y),
                      wq2 = pk2(wq.z, wq.z), wq3 = pk2(wq.w, wq.w);
            const ull wk0 = pk2(wk.x, wk.x), wk1 = pk2(wk.y, wk.y),
                      wk2 = pk2(wk.z, wk.z), wk3 = pk2(wk.w, wk.w);

            accq[0] = f2fma(wq0, x0,  accq[0]);  acck[0] = f2fma(wk0, x0,  acck[0]);
            accq[1] = f2fma(wq1, x1,  accq[1]);  acck[1] = f2fma(wk1, x1,  acck[1]);
            accq[2] = f2fma(wq1, x2,  accq[2]);  acck[2] = f2fma(wk1, x2,  acck[2]);
            accq[3] = f2fma(wq1, x3,  accq[3]);  acck[3] = f2fma(wk1, x3,  acck[3]);
            accq[4] = f2fma(wq2, x4v, accq[4]);  acck[4] = f2fma(wk2, x4v, acck[4]);
            accq[5] = f2fma(wq2, x5,  accq[5]);  acck[5] = f2fma(wk2, x5,  acck[5]);
            accq[6] = f2fma(wq2, x6,  accq[6]);  acck[6] = f2fma(wk2, x6,  acck[6]);
            accq[7] = f2fma(wq3, x7,  accq[7]);  acck[7] = f2fma(wk3, x7,  acck[7]);
        }
    }

    // Unpack: arr[v], v = pj*16 + bl*8 + i  (bl=0 -> b=p, bl=1 -> b=p+2)
    float arr[32];
#pragma unroll
    for (int i = 0; i < 8; i++) {
        upk2(accq[i], arr[i],      arr[8 + i]);
        upk2(acck[i], arr[16 + i], arr[24 + i]);
    }

    // Truncated butterfly: offsets 16,8,4,2 -> reduce over the 16 same-parity
    // lanes; lane l ends with values (l&30) and (l&30)|1.
#pragma unroll
    for (int off = 16; off >= 2; off >>= 1) {
        const bool up = (lane & off) != 0;
#pragma unroll
        for (int k = 0; k < 16; k++) {
            if (k < off) {
                float send  = up ? arr[k] : arr[k + off];
                float other = __shfl_xor_sync(0xffffffffu, send, off);
                arr[k] = (up ? arr[k + off] : arr[k]) + other;
            }
        }
    }

    const int vbase = lane & 30;
#pragma unroll
    for (int k = 0; k < 2; k++) {
        const int v  = vbase | k;
        const int pj = v >> 4;
        const int bl = (v >> 3) & 1;
        const int i  = v & 7;
        const int b  = p + 2 * bl;
        part_buf[(((size_t)eighth * SEQ + n) * 2 + pj) * 32 + b * 8 + i] = arr[k];
    }
}

// ---------------------------------------------------------------------------
// Kernel A2: combine the 8 m-eighth partials, add bias, LayerNorm, fp16
// cast. One thread per (n, proj, b) = 8192 threads.
// ---------------------------------------------------------------------------
__global__ void __launch_bounds__(256) ln_finalize_kernel(
    const float* __restrict__ bq,
    const float* __restrict__ bk,
    const float* __restrict__ gamma,
    const float* __restrict__ beta)
{
    const int t  = blockIdx.x * 256 + threadIdx.x;
    const int n  = t >> 3;
    const int pj = (t >> 2) & 1;
    const int b  = t & 3;

    float v[8];
#pragma unroll
    for (int i = 0; i < 8; i++) v[i] = 0.0f;
#pragma unroll
    for (int q = 0; q < 8; q++) {
        const float* p = part_buf + (((size_t)q * SEQ + n) * 2 + pj) * 32 + b * 8;
#pragma unroll
        for (int i = 0; i < 8; i++) v[i] += p[i];
    }
    v[0] += pj ? bk[n] : bq[n];   // bias on scalar comp, before LN

    float mu = 0.0f;
#pragma unroll
    for (int i = 0; i < 8; i++) mu += v[i];
    mu *= 0.125f;
    float var = 0.0f;
#pragma unroll
    for (int i = 0; i < 8; i++) { float d = v[i] - mu; var = fmaf(d, d, var); }
    const float r = rsqrtf(var * 0.125f + 1e-5f);

    __half2* dst = reinterpret_cast<__half2*>(
        (pj ? k_buf : q_buf) + ((size_t)b * SEQ + n) * 8);
#pragma unroll
    for (int j = 0; j < 4; j++) {
        float a0 = (v[2*j]   - mu) * r * gamma[2*j]   + beta[2*j];
        float a1 = (v[2*j+1] - mu) * r * gamma[2*j+1] + beta[2*j+1];
        dst[j] = __floats2half2_rn(a0, a1);
    }
}

// ---------------------------------------------------------------------------
// Kernel B: geometric product out[b,n,m,:] = GP(q[b,n], k[b,m]), Cl(3,0),
// basis [1, e1, e2, e3, e12, e13, e23, e123].
// Even lanes compute comps 0..3, odd lanes comps 4..7 via duality
// out o (-e123). Thread covers m-pair (m_a, m_a+16) in f32x2 lanes; each
// warp-STG is 512B contiguous. 8 n-rows per block (2048 blocks), q tile
// pre-packed as (q,q) ulls in smem -> per-nl broadcast LDS.64.
// ---------------------------------------------------------------------------
__global__ void __launch_bounds__(256) gp_kernel(float* __restrict__ out)
{
    __shared__ ull qsp[8][8];

    const int b      = blockIdx.y;
    const int ntile  = blockIdx.x >> 2;     // 0..127
    const int mchunk = blockIdx.x & 3;      // 0..3
    const int n0     = ntile * 8;
    const int t      = threadIdx.x;
    const int w      = t >> 5;
    const int lane   = t & 31;
    const int half   = lane & 1;            // 0: comps 0-3, 1: comps 4-7
    const int mm     = lane >> 1;           // 0..15
    const int m_a    = mchunk * 256 + w * 32 + mm;   // pair partner: m_a + 16

    // q tile: 8 rows x 8 comps, stored duplicated-packed for direct LDS.64
    if (t < 64) {
        const float v = __half2float(
            q_buf[((size_t)b * SEQ + n0 + (t >> 3)) * 8 + (t & 7)]);
        qsp[t >> 3][t & 7] = pk2(v, v);
    }

    // K for both m's of this thread
    const uint4* kb4 = reinterpret_cast<const uint4*>(k_buf) + (size_t)b * SEQ;
    const uint4 kva = __ldg(&kb4[m_a]);
    const uint4 kvb = __ldg(&kb4[m_a + 16]);

    float A[8], B[8];
    {
        float2 f;
        f = __half22float2(*reinterpret_cast<const __half2*>(&kva.x)); A[0]=f.x; A[1]=f.y;
        f = __half22float2(*reinterpret_cast<const __half2*>(&kva.y)); A[2]=f.x; A[3]=f.y;
        f = __half22float2(*reinterpret_cast<const __half2*>(&kva.z)); A[4]=f.x; A[5]=f.y;
        f = __half22float2(*reinterpret_cast<const __half2*>(&kva.w)); A[6]=f.x; A[7]=f.y;
        f = __half22float2(*reinterpret_cast<const __half2*>(&kvb.x)); B[0]=f.x; B[1]=f.y;
        f = __half22float2(*reinterpret_cast<const __half2*>(&kvb.y)); B[2]=f.x; B[3]=f.y;
        f = __half22float2(*reinterpret_cast<const __half2*>(&kvb.z)); B[4]=f.x; B[5]=f.y;
        f = __half22float2(*reinterpret_cast<const __half2*>(&kvb.w)); B[6]=f.x; B[7]=f.y;
    }
    if (half) {  // K' = k o (-e123): {k7, k6, -k5, k4, -k3, k2, -k1, -k0}
        float tA[8], tB[8];
        tA[0]= A[7]; tA[1]= A[6]; tA[2]=-A[5]; tA[3]= A[4];
        tA[4]=-A[3]; tA[5]= A[2]; tA[6]=-A[1]; tA[7]=-A[0];
        tB[0]= B[7]; tB[1]= B[6]; tB[2]=-B[5]; tB[3]= B[4];
        tB[4]=-B[3]; tB[5]= B[2]; tB[6]=-B[1]; tB[7]=-B[0];
#pragma unroll
        for (int i = 0; i < 8; i++) { A[i] = tA[i]; B[i] = tB[i]; }
    }
    const ull K0 = pk2(A[0],B[0]), K1 = pk2(A[1],B[1]), K2 = pk2(A[2],B[2]),
              K3 = pk2(A[3],B[3]), K4 = pk2(A[4],B[4]), K5 = pk2(A[5],B[5]),
              K6 = pk2(A[6],B[6]), K7 = pk2(A[7],B[7]);
    const ull NK1 = pk2(-A[1],-B[1]), NK2 = pk2(-A[2],-B[2]),
              NK4 = pk2(-A[4],-B[4]), NK5 = pk2(-A[5],-B[5]),
              NK6 = pk2(-A[6],-B[6]), NK7 = pk2(-A[7],-B[7]);
    const ull MNEG1 = pk2(-1.0f, -1.0f);

    __syncthreads();

    // float4 index of this thread's first chunk for nl=0
    size_t fi = ((size_t)(b * SEQ + n0) * SEQ + m_a) * 2 + half;
    float4* o4 = reinterpret_cast<float4*>(out);

#pragma unroll 1
    for (int nl = 0; nl < 8; nl++) {
        const ull P0 = qsp[nl][0], P1 = qsp[nl][1], P2 = qsp[nl][2], P3 = qsp[nl][3],
                  P4 = qsp[nl][4], P5 = qsp[nl][5], P6 = qsp[nl][6], P7 = qsp[nl][7];

        // o0..o3 of q o K (verified table; odd lanes' K is pre-transformed)
        ull a0 = f2mul(P0, K0);
        ull a1 = f2mul(P0, K1);
        ull a2 = f2mul(P0, K2);
        ull a3 = f2mul(P0, K3);
        a0 = f2fma(P1, K1,  a0); a1 = f2fma(P1, K0,  a1); a2 = f2fma(P1, K4,  a2); a3 = f2fma(P1, K5,  a3);
        a0 = f2fma(P2, K2,  a0); a1 = f2fma(P2, NK4, a1); a2 = f2fma(P2, K0,  a2); a3 = f2fma(P2, K6,  a3);
        a0 = f2fma(P3, K3,  a0); a1 = f2fma(P3, NK5, a1); a2 = f2fma(P3, NK6, a2); a3 = f2fma(P3, K0,  a3);
        a0 = f2fma(P4, NK4, a0); a1 = f2fma(P4, K2,  a1); a2 = f2fma(P4, NK1, a2); a3 = f2fma(P4, NK7, a3);
        a0 = f2fma(P5, NK5, a0); a1 = f2fma(P5, K3,  a1); a2 = f2fma(P5, K7,  a2); a3 = f2fma(P5, NK1, a3);
        a0 = f2fma(P6, NK6, a0); a1 = f2fma(P6, NK7, a1); a2 = f2fma(P6, K3,  a2); a3 = f2fma(P6, NK2, a3);
        a0 = f2fma(P7, NK7, a0); a1 = f2fma(P7, NK6, a1); a2 = f2fma(P7, K5,  a2); a3 = f2fma(P7, NK4, a3);

        // odd lanes: (out4,out5,out6,out7) = (o3, -o2, o1, o0)
        const ull na2 = f2mul(a2, MNEG1);
        const ull s0 = half ? a3  : a0;
        const ull s1 = half ? na2 : a1;
        const ull s2 = half ? a1  : a2;
        const ull s3 = half ? a0  : a3;

        float e0,e1,e2,e3, f0,f1,f2,f3;
        upk2(s0, e0, f0); upk2(s1, e1, f1); upk2(s2, e2, f2); upk2(s3, e3, f3);

        __stcs(&o4[fi],      make_float4(e0, e1, e2, e3));   // m_a
        __stcs(&o4[fi + 32], make_float4(f0, f1, f2, f3));   // m_a + 16
        fi += 2048;   // next n row
    }
}

extern "C" void kernel_launch(void* const* d_in, const int* in_sizes, int n_in,
                              void* d_out, int out_size)
{
    (void)in_sizes; (void)n_in; (void)out_size;
    const float* x     = (const float*)d_in[0];
    const float* Wq    = (const float*)d_in[1];
    const float* bq    = (const float*)d_in[2];
    const float* Wk    = (const float*)d_in[3];
    const float* bk    = (const float*)d_in[4];
    const float* gamma = (const float*)d_in[5];
    const float* beta  = (const float*)d_in[6];
    float* out = (float*)d_out;

    cudaFuncSetAttribute(proj_partial_kernel,
                         cudaFuncAttributeMaxDynamicSharedMemorySize,
                         PROJ_SMEM_BYTES);
    proj_partial_kernel<<<dim3(128, 8), 256, PROJ_SMEM_BYTES>>>(x, Wq, Wk);
    ln_finalize_kernel<<<32, 256>>>(bq, bk, gamma, beta);
    gp_kernel<<<dim3(512, 4), 256>>>(out);
}

// round 16
// speedup vs baseline: 1.1087x; 1.0492x over previous
#include <cuda_runtime.h>
#include <cuda_fp16.h>
#include <cuda_pipeline.h>
#include <cstdint>

#define SEQ 1024

// fp16 q/k scratch (allocation-free: __device__ globals)
__device__ __half q_buf[4 * SEQ * 8];
__device__ __half k_buf[4 * SEQ * 8];
// partial-sum scratch: [eighth][n][proj][b][8 comps]
__device__ float part_buf[8 * SEQ * 2 * 4 * 8];

typedef unsigned long long ull;

// dynamic smem layout for proj: xs (2304 ull = 18KB) then ws (2048 float4 = 32KB)
#define PROJ_SMEM_BYTES (2304 * 8 + 8 * 4 * 64 * 16)

// ---- packed f32x2 helpers (Blackwell) ----
__device__ __forceinline__ ull pk2(float lo, float hi) {
    ull d;
    asm("mov.b64 %0, {%1, %2};" : "=l"(d)
        : "r"(__float_as_uint(lo)), "r"(__float_as_uint(hi)));
    return d;
}
__device__ __forceinline__ void upk2(ull d, float& lo, float& hi) {
    unsigned a, b;
    asm("mov.b64 {%0, %1}, %2;" : "=r"(a), "=r"(b) : "l"(d));
    lo = __uint_as_float(a); hi = __uint_as_float(b);
}
__device__ __forceinline__ ull f2fma(ull a, ull b, ull c) {
    ull d;
    asm("fma.rn.f32x2 %0, %1, %2, %3;" : "=l"(d) : "l"(a), "l"(b), "l"(c));
    return d;
}
__device__ __forceinline__ ull f2mul(ull a, ull b) {
    ull d;
    asm("mul.rn.f32x2 %0, %1, %2;" : "=l"(d) : "l"(a), "l"(b));
    return d;
}

// ---------------------------------------------------------------------------
// Kernel A1: partial mvlinear, batch-packed f32x2, both projections per warp,
// W fully prefetched through a 4-deep cp.async pipeline (all 4 chunks issued
// before the main loop; loop only waits and consumes). Dynamic smem (50 KB);
// 4 blocks/SM = 200 KB of the 228 KB carveout.
// Block = (8 n rows, m-eighth of 128). Warp = one n. Lane = (m_local =
// lane>>1, parity p = lane&1 -> batches {p, p+2} packed in f32x2).
// ---------------------------------------------------------------------------
__global__ void __launch_bounds__(256, 4) proj_partial_kernel(
    const float* __restrict__ x,     // [4,1024,8]
    const float* __restrict__ Wq,    // [1024,1024,4]
    const float* __restrict__ Wk)    // [1024,1024,4]
{
    extern __shared__ ull dyn_smem[];
    ull*    xs = dyn_smem;                                   // 128 m * 9 units * 16B
    float4* ws = reinterpret_cast<float4*>(dyn_smem + 2304); // [warp][stage][64]

    const int t      = threadIdx.x;
    const int w      = t >> 5;
    const int lane   = t & 31;
    const int p      = lane & 1;
    const int ntile  = blockIdx.x;        // 0..127
    const int eighth = blockIdx.y;        // 0..7
    const int n      = ntile * 8 + w;
    const int q0     = eighth * 128;

    const float4* wqr = reinterpret_cast<const float4*>(Wq) + (size_t)n * SEQ + q0;
    const float4* wkr = reinterpret_cast<const float4*>(Wk) + (size_t)n * SEQ + q0;
    float4* wsw = ws + w * 4 * 64;

    // ---- prologue: issue ALL 4 W chunks into 4 stages ----
#pragma unroll
    for (int c = 0; c < 4; c++) {
        __pipeline_memcpy_async(&wsw[c * 64 + lane],      &wqr[c * 32 + lane], 16);
        __pipeline_memcpy_async(&wsw[c * 64 + 32 + lane], &wkr[c * 32 + lane], 16);
        __pipeline_commit();
    }

    // ---- stage x eighth, batch-pair packed: items (m 0..127, p 0..1) ----
    {
        const float4* x4 = reinterpret_cast<const float4*>(x);
        const int m  = t >> 1;
        const int pp = t & 1;
        const float4 a0 = __ldg(&x4[((size_t)pp * SEQ + q0 + m) * 2]);
        const float4 a1 = __ldg(&x4[((size_t)pp * SEQ + q0 + m) * 2 + 1]);
        const float4 b0 = __ldg(&x4[((size_t)(pp + 2) * SEQ + q0 + m) * 2]);
        const float4 b1 = __ldg(&x4[((size_t)(pp + 2) * SEQ + q0 + m) * 2 + 1]);
        ull* dst = xs + (size_t)(m * 9 + pp * 4) * 2;
        dst[0] = pk2(a0.x, b0.x); dst[1] = pk2(a0.y, b0.y);
        dst[2] = pk2(a0.z, b0.z); dst[3] = pk2(a0.w, b0.w);
        dst[4] = pk2(a1.x, b1.x); dst[5] = pk2(a1.y, b1.y);
        dst[6] = pk2(a1.z, b1.z); dst[7] = pk2(a1.w, b1.w);
    }

    ull accq[8], acck[8];
#pragma unroll
    for (int i = 0; i < 8; i++) { accq[i] = 0ull; acck[i] = 0ull; }

    __syncthreads();   // xs visible

#pragma unroll
    for (int c = 0; c < 4; c++) {
        __pipeline_wait_prior(3 - c);   // chunk c's group complete
        __syncwarp();

#pragma unroll
        for (int sub = 0; sub < 2; sub++) {
            const int r  = sub * 16 + (lane >> 1);      // row in chunk
            const int ml = c * 32 + r;                  // row in eighth
            const float4 wq = wsw[c * 64 + r];
            const float4 wk = wsw[c * 64 + 32 + r];
            const ull* xr = xs + (size_t)(ml * 9 + p * 4) * 2;
            const ull x0 = xr[0], x1 = xr[1], x2 = xr[2], x3 = xr[3];
            const ull x4v = xr[4], x5 = xr[5], x6 = xr[6], x7 = xr[7];

            const ull wq0 = pk2(wq.x, wq.x), wq1 = pk2(wq.y, wq.y),
                      wq2 = pk2(wq.z, wq.z), wq3 = pk2(wq.w, wq.w);
            const ull wk0 = pk2(wk.x, wk.x), wk1 = pk2(wk.y, wk.y),
                      wk2 = pk2(wk.z, wk.z), wk3 = pk2(wk.w, wk.w);

            accq[0] = f2fma(wq0, x0,  accq[0]);  acck[0] = f2fma(wk0, x0,  acck[0]);
            accq[1] = f2fma(wq1, x1,  accq[1]);  acck[1] = f2fma(wk1, x1,  acck[1]);
            accq[2] = f2fma(wq1, x2,  accq[2]);  acck[2] = f2fma(wk1, x2,  acck[2]);
            accq[3] = f2fma(wq1, x3,  accq[3]);  acck[3] = f2fma(wk1, x3,  acck[3]);
            accq[4] = f2fma(wq2, x4v, accq[4]);  acck[4] = f2fma(wk2, x4v, acck[4]);
            accq[5] = f2fma(wq2, x5,  accq[5]);  acck[5] = f2fma(wk2, x5,  acck[5]);
            accq[6] = f2fma(wq2, x6,  accq[6]);  acck[6] = f2fma(wk2, x6,  acck[6]);
            accq[7] = f2fma(wq3, x7,  accq[7]);  acck[7] = f2fma(wk3, x7,  acck[7]);
        }
    }

    // Unpack: arr[v], v = pj*16 + bl*8 + i  (bl=0 -> b=p, bl=1 -> b=p+2)
    float arr[32];
#pragma unroll
    for (int i = 0; i < 8; i++) {
        upk2(accq[i], arr[i],      arr[8 + i]);
        upk2(acck[i], arr[16 + i], arr[24 + i]);
    }

    // Truncated butterfly: offsets 16,8,4,2 -> reduce over the 16 same-parity
    // lanes; lane l ends with values (l&30) and (l&30)|1.
#pragma unroll
    for (int off = 16; off >= 2; off >>= 1) {
        const bool up = (lane & off) != 0;
#pragma unroll
        for (int k = 0; k < 16; k++) {
            if (k < off) {
                float send  = up ? arr[k] : arr[k + off];
                float other = __shfl_xor_sync(0xffffffffu, send, off);
                arr[k] = (up ? arr[k + off] : arr[k]) + other;
            }
        }
    }

    const int vbase = lane & 30;
#pragma unroll
    for (int k = 0; k < 2; k++) {
        const int v  = vbase | k;
        const int pj = v >> 4;
        const int bl = (v >> 3) & 1;
        const int i  = v & 7;
        const int b  = p + 2 * bl;
        part_buf[(((size_t)eighth * SEQ + n) * 2 + pj) * 32 + b * 8 + i] = arr[k];
    }
}

// ---------------------------------------------------------------------------
// Kernel A2: combine the 8 m-eighth partials, add bias, LayerNorm, fp16
// cast. One thread per (n, proj, b) = 8192 threads, 64 blocks of 128 for
// wider SM spread (gather is latency-bound).
// ---------------------------------------------------------------------------
__global__ void __launch_bounds__(128) ln_finalize_kernel(
    const float* __restrict__ bq,
    const float* __restrict__ bk,
    const float* __restrict__ gamma,
    const float* __restrict__ beta)
{
    const int t  = blockIdx.x * 128 + threadIdx.x;
    const int n  = t >> 3;
    const int pj = (t >> 2) & 1;
    const int b  = t & 3;

    float v[8];
#pragma unroll
    for (int i = 0; i < 8; i++) v[i] = 0.0f;
#pragma unroll
    for (int q = 0; q < 8; q++) {
        const float* p = part_buf + (((size_t)q * SEQ + n) * 2 + pj) * 32 + b * 8;
#pragma unroll
        for (int i = 0; i < 8; i++) v[i] += p[i];
    }
    v[0] += pj ? bk[n] : bq[n];   // bias on scalar comp, before LN

    float mu = 0.0f;
#pragma unroll
    for (int i = 0; i < 8; i++) mu += v[i];
    mu *= 0.125f;
    float var = 0.0f;
#pragma unroll
    for (int i = 0; i < 8; i++) { float d = v[i] - mu; var = fmaf(d, d, var); }
    const float r = rsqrtf(var * 0.125f + 1e-5f);

    __half2* dst = reinterpret_cast<__half2*>(
        (pj ? k_buf : q_buf) + ((size_t)b * SEQ + n) * 8);
#pragma unroll
    for (int j = 0; j < 4; j++) {
        float a0 = (v[2*j]   - mu) * r * gamma[2*j]   + beta[2*j];
        float a1 = (v[2*j+1] - mu) * r * gamma[2*j+1] + beta[2*j+1];
        dst[j] = __floats2half2_rn(a0, a1);
    }
}

// ---------------------------------------------------------------------------
// Kernel B: geometric product out[b,n,m,:] = GP(q[b,n], k[b,m]), Cl(3,0),
// basis [1, e1, e2, e3, e12, e13, e23, e123].
// Even lanes compute comps 0..3, odd lanes comps 4..7 via duality
// out o (-e123). Thread covers m-pair (m_a, m_a+16) in f32x2 lanes; each
// warp-STG is 512B contiguous. 8 n-rows per block (2048 blocks), q tile
// pre-packed as (q,q) ulls in smem; per-nl 4x broadcast LDS.128 (ulonglong2).
// __launch_bounds__(256,6): regs<=42 -> 6 blocks/SM resident.
// ---------------------------------------------------------------------------
__global__ void __launch_bounds__(256, 6) gp_kernel(float* __restrict__ out)
{
    __shared__ __align__(16) ull qsp[8][8];

    const int b      = blockIdx.y;
    const int ntile  = blockIdx.x >> 2;     // 0..127
    const int mchunk = blockIdx.x & 3;      // 0..3
    const int n0     = ntile * 8;
    const int t      = threadIdx.x;
    const int w      = t >> 5;
    const int lane   = t & 31;
    const int half   = lane & 1;            // 0: comps 0-3, 1: comps 4-7
    const int mm     = lane >> 1;           // 0..15
    const int m_a    = mchunk * 256 + w * 32 + mm;   // pair partner: m_a + 16

    // q tile: 8 rows x 8 comps, stored duplicated-packed for direct LDS
    if (t < 64) {
        const float v = __half2float(
            q_buf[((size_t)b * SEQ + n0 + (t >> 3)) * 8 + (t & 7)]);
        qsp[t >> 3][t & 7] = pk2(v, v);
    }

    // K for both m's of this thread
    const uint4* kb4 = reinterpret_cast<const uint4*>(k_buf) + (size_t)b * SEQ;
    const uint4 kva = __ldg(&kb4[m_a]);
    const uint4 kvb = __ldg(&kb4[m_a + 16]);

    float A[8], B[8];
    {
        float2 f;
        f = __half22float2(*reinterpret_cast<const __half2*>(&kva.x)); A[0]=f.x; A[1]=f.y;
        f = __half22float2(*reinterpret_cast<const __half2*>(&kva.y)); A[2]=f.x; A[3]=f.y;
        f = __half22float2(*reinterpret_cast<const __half2*>(&kva.z)); A[4]=f.x; A[5]=f.y;
        f = __half22float2(*reinterpret_cast<const __half2*>(&kva.w)); A[6]=f.x; A[7]=f.y;
        f = __half22float2(*reinterpret_cast<const __half2*>(&kvb.x)); B[0]=f.x; B[1]=f.y;
        f = __half22float2(*reinterpret_cast<const __half2*>(&kvb.y)); B[2]=f.x; B[3]=f.y;
        f = __half22float2(*reinterpret_cast<const __half2*>(&kvb.z)); B[4]=f.x; B[5]=f.y;
        f = __half22float2(*reinterpret_cast<const __half2*>(&kvb.w)); B[6]=f.x; B[7]=f.y;
    }
    if (half) {  // K' = k o (-e123): {k7, k6, -k5, k4, -k3, k2, -k1, -k0}
        float tA[8], tB[8];
        tA[0]= A[7]; tA[1]= A[6]; tA[2]=-A[5]; tA[3]= A[4];
        tA[4]=-A[3]; tA[5]= A[2]; tA[6]=-A[1]; tA[7]=-A[0];
        tB[0]= B[7]; tB[1]= B[6]; tB[2]=-B[5]; tB[3]= B[4];
        tB[4]=-B[3]; tB[5]= B[2]; tB[6]=-B[1]; tB[7]=-B[0];
#pragma unroll
        for (int i = 0; i < 8; i++) { A[i] = tA[i]; B[i] = tB[i]; }
    }
    const ull K0 = pk2(A[0],B[0]), K1 = pk2(A[1],B[1]), K2 = pk2(A[2],B[2]),
              K3 = pk2(A[3],B[3]), K4 = pk2(A[4],B[4]), K5 = pk2(A[5],B[5]),
              K6 = pk2(A[6],B[6]), K7 = pk2(A[7],B[7]);
    const ull NK1 = pk2(-A[1],-B[1]), NK2 = pk2(-A[2],-B[2]),
              NK4 = pk2(-A[4],-B[4]), NK5 = pk2(-A[5],-B[5]),
              NK6 = pk2(-A[6],-B[6]), NK7 = pk2(-A[7],-B[7]);
    const ull MNEG1 = pk2(-1.0f, -1.0f);

    __syncthreads();

    // float4 index of this thread's first chunk for nl=0
    size_t fi = ((size_t)(b * SEQ + n0) * SEQ + m_a) * 2 + half;
    float4* o4 = reinterpret_cast<float4*>(out);

#pragma unroll 1
    for (int nl = 0; nl < 8; nl++) {
        const ulonglong2* qr = reinterpret_cast<const ulonglong2*>(qsp[nl]);
        const ulonglong2 v0 = qr[0], v1 = qr[1], v2 = qr[2], v3 = qr[3];
        const ull P0 = v0.x, P1 = v0.y, P2 = v1.x, P3 = v1.y,
                  P4 = v2.x, P5 = v2.y, P6 = v3.x, P7 = v3.y;

        // o0..o3 of q o K (verified table; odd lanes' K is pre-transformed)
        ull a0 = f2mul(P0, K0);
        ull a1 = f2mul(P0, K1);
        ull a2 = f2mul(P0, K2);
        ull a3 = f2mul(P0, K3);
        a0 = f2fma(P1, K1,  a0); a1 = f2fma(P1, K0,  a1); a2 = f2fma(P1, K4,  a2); a3 = f2fma(P1, K5,  a3);
        a0 = f2fma(P2, K2,  a0); a1 = f2fma(P2, NK4, a1); a2 = f2fma(P2, K0,  a2); a3 = f2fma(P2, K6,  a3);
        a0 = f2fma(P3, K3,  a0); a1 = f2fma(P3, NK5, a1); a2 = f2fma(P3, NK6, a2); a3 = f2fma(P3, K0,  a3);
        a0 = f2fma(P4, NK4, a0); a1 = f2fma(P4, K2,  a1); a2 = f2fma(P4, NK1, a2); a3 = f2fma(P4, NK7, a3);
        a0 = f2fma(P5, NK5, a0); a1 = f2fma(P5, K3,  a1); a2 = f2fma(P5, K7,  a2); a3 = f2fma(P5, NK1, a3);
        a0 = f2fma(P6, NK6, a0); a1 = f2fma(P6, NK7, a1); a2 = f2fma(P6, K3,  a2); a3 = f2fma(P6, NK2, a3);
        a0 = f2fma(P7, NK7, a0); a1 = f2fma(P7, NK6, a1); a2 = f2fma(P7, K5,  a2); a3 = f2fma(P7, NK4, a3);

        // odd lanes: (out4,out5,out6,out7) = (o3, -o2, o1, o0)
        const ull na2 = f2mul(a2, MNEG1);
        const ull s0 = half ? a3  : a0;
        const ull s1 = half ? na2 : a1;
        const ull s2 = half ? a1  : a2;
        const ull s3 = half ? a0  : a3;

        float e0,e1,e2,e3, f0,f1,f2,f3;
        upk2(s0, e0, f0); upk2(s1, e1, f1); upk2(s2, e2, f2); upk2(s3, e3, f3);

        __stcs(&o4[fi],      make_float4(e0, e1, e2, e3));   // m_a
        __stcs(&o4[fi + 32], make_float4(f0, f1, f2, f3));   // m_a + 16
        fi += 2048;   // next n row
    }
}

extern "C" void kernel_launch(void* const* d_in, const int* in_sizes, int n_in,
                              void* d_out, int out_size)
{
    (void)in_sizes; (void)n_in; (void)out_size;
    const float* x     = (const float*)d_in[0];
    const float* Wq    = (const float*)d_in[1];
    const float* bq    = (const float*)d_in[2];
    const float* Wk    = (const float*)d_in[3];
    const float* bk    = (const float*)d_in[4];
    const float* gamma = (const float*)d_in[5];
    const float* beta  = (const float*)d_in[6];
    float* out = (float*)d_out;

    cudaFuncSetAttribute(proj_partial_kernel,
                         cudaFuncAttributeMaxDynamicSharedMemorySize,
                         PROJ_SMEM_BYTES);
    proj_partial_kernel<<<dim3(128, 8), 256, PROJ_SMEM_BYTES>>>(x, Wq, Wk);
    ln_finalize_kernel<<<64, 128>>>(bq, bk, gamma, beta);
    gp_kernel<<<dim3(512, 4), 256>>>(out);
}